// round 11
// baseline (speedup 1.0000x reference)
#include <cuda_runtime.h>
#include <cuda_bf16.h>

#define MAX_SEG 16384
#define PAD 32   // one float counter per 128B L2 line

// Padded scatter accumulators: track/hit separated, one counter per 128B
// line. Zero-initialized at module load; corr_kernel self-cleans after
// reading, so every launch starts from a clean state.
__device__ float g_track[MAX_SEG * PAD];
__device__ float g_hit[MAX_SEG * PAD];

// Packed table for the gather phase: ONE 16B read per hit.
//   x = e_track_raw  y = e_track_corr  z = e_hit_raw  w = e_hit_corr
__device__ float4 g_shower[MAX_SEG];

__device__ __forceinline__ void stcs_f4(float4* p, float4 v) {
    asm volatile("st.global.cs.v4.f32 [%0], {%1,%2,%3,%4};"
                 :: "l"(p), "f"(v.x), "f"(v.y), "f"(v.z), "f"(v.w)
                 : "memory");
}
__device__ __forceinline__ int4 ldcs_i4(const int4* p) {
    int4 v;
    asm volatile("ld.global.cs.v4.s32 {%0,%1,%2,%3}, [%4];"
                 : "=r"(v.x), "=r"(v.y), "=r"(v.z), "=r"(v.w) : "l"(p));
    return v;
}
__device__ __forceinline__ float4 ldcs_f4(const float4* p) {
    float4 v;
    asm volatile("ld.global.cs.v4.f32 {%0,%1,%2,%3}, [%4];"
                 : "=f"(v.x), "=f"(v.y), "=f"(v.z), "=f"(v.w) : "l"(p));
    return v;
}

// ---------------------------------------------------------------------------
// Kernel 1: scatter — grid-stride, 8 hits/iter, evict-first streaming loads
// (keep L2 for the hot accumulator lines), then 8 predicated REDs.
// Noise hits (sid == -1) contribute exactly 0 in the reference -> skipped.
// recHitID==1 -> track, ==0 -> hit.
// ---------------------------------------------------------------------------
__global__ void __launch_bounds__(256, 8) scatter8_gs_kernel(
        const int* __restrict__ sid,
        const float* __restrict__ energy,
        const int* __restrict__ rid,
        int ngroups,           // n/8 groups of 8 hits
        int n) {
    int stride = gridDim.x * blockDim.x;
    for (int t = blockIdx.x * blockDim.x + threadIdx.x; t < ngroups;
         t += stride) {
        int4   s0 = ldcs_i4((const int4*)(sid)      + 2*t);
        int4   s1 = ldcs_i4((const int4*)(sid)      + 2*t + 1);
        float4 e0 = ldcs_f4((const float4*)(energy) + 2*t);
        float4 e1 = ldcs_f4((const float4*)(energy) + 2*t + 1);
        int4   r0 = ldcs_i4((const int4*)(rid)      + 2*t);
        int4   r1 = ldcs_i4((const int4*)(rid)      + 2*t + 1);
        int   s[8] = {s0.x, s0.y, s0.z, s0.w, s1.x, s1.y, s1.z, s1.w};
        float e[8] = {e0.x, e0.y, e0.z, e0.w, e1.x, e1.y, e1.z, e1.w};
        int   r[8] = {r0.x, r0.y, r0.z, r0.w, r1.x, r1.y, r1.z, r1.w};
#pragma unroll
        for (int k = 0; k < 8; k++) {
            if (s[k] >= 0) {
                float* p = (r[k] == 1) ? &g_track[(s[k] + 1) * PAD]
                                       : &g_hit[(s[k] + 1) * PAD];
                atomicAdd(p, e[k]);
            }
        }
    }
    // Tail (n % 8 hits): one thread, <= 7 ops.
    if (blockIdx.x == 0 && threadIdx.x == 0) {
        for (int i = ngroups * 8; i < n; i++) {
            int sv = sid[i];
            if (sv >= 0) {
                float* p = (rid[i] == 1) ? &g_track[(sv + 1) * PAD]
                                         : &g_hit[(sv + 1) * PAD];
                atomicAdd(p, energy[i]);
            }
        }
    }
}

// ---------------------------------------------------------------------------
// Kernel 2: per-shower correction + repack into the float4 table + self-clean.
// corr[s] (s>=1) = pcf_ext[alpha_idx[s-1]], pcf_ext[j] = pcf[j] if j < n_hits
// and sid[j] != -1, else 0. corr[0] = 0.
// ---------------------------------------------------------------------------
__global__ void corr_kernel(const int* __restrict__ sid,
                            const float* __restrict__ pcf,
                            const int* __restrict__ a_tracks,
                            const int* __restrict__ a_hits,
                            int n_hits, int nseg) {
    int s = blockIdx.x * blockDim.x + threadIdx.x;
    if (s >= nseg) return;
    float ct = 0.f, ch = 0.f;
    if (s > 0) {
        int jt = a_tracks[s - 1];
        if (jt >= 0 && jt < n_hits && __ldg(sid + jt) != -1) ct = __ldg(pcf + jt);
        int jh = a_hits[s - 1];
        if (jh >= 0 && jh < n_hits && __ldg(sid + jh) != -1) ch = __ldg(pcf + jh);
    }
    float et = g_track[s * PAD];
    float eh = g_hit[s * PAD];
    g_shower[s] = make_float4(et, et * ct, eh, eh * ch);
    g_track[s * PAD] = 0.f;   // clean for the next launch
    g_hit[s * PAD]   = 0.f;
}

// ---------------------------------------------------------------------------
// Kernel 3: gather — grid-stride one wave, 8 hits/iter: 2 int4 sid loads ->
// 8 independent random 16B table reads in flight -> 8 coalesced float4
// STREAMING stores. Output layout (reference tuple order):
//   [0,n) e_track_raw [n,2n) e_track_corr [2n,3n) e_hit_raw [3n,4n) e_hit_corr
// ---------------------------------------------------------------------------
__global__ void __launch_bounds__(256, 8) gather8_gs_kernel(
        const int* __restrict__ sid,
        float* __restrict__ out,
        int noct, int n) {            // noct = n/8
    int stride = gridDim.x * blockDim.x;
    int nq = n / 4;                   // float4 stride per output stream
    float4* o = (float4*)out;
    for (int t = blockIdx.x * blockDim.x + threadIdx.x; t < noct;
         t += stride) {
        int4 a = __ldg((const int4*)(sid) + 2*t);
        int4 b = __ldg((const int4*)(sid) + 2*t + 1);
        float4 v0 = g_shower[a.x + 1];
        float4 v1 = g_shower[a.y + 1];
        float4 v2 = g_shower[a.z + 1];
        float4 v3 = g_shower[a.w + 1];
        float4 v4 = g_shower[b.x + 1];
        float4 v5 = g_shower[b.y + 1];
        float4 v6 = g_shower[b.z + 1];
        float4 v7 = g_shower[b.w + 1];
        long q = 2l * t;
        stcs_f4(o + q,              make_float4(v0.x, v1.x, v2.x, v3.x));
        stcs_f4(o + q + 1,          make_float4(v4.x, v5.x, v6.x, v7.x));
        stcs_f4(o + q + nq,         make_float4(v0.y, v1.y, v2.y, v3.y));
        stcs_f4(o + q + nq + 1,     make_float4(v4.y, v5.y, v6.y, v7.y));
        stcs_f4(o + q + 2l*nq,      make_float4(v0.z, v1.z, v2.z, v3.z));
        stcs_f4(o + q + 2l*nq + 1,  make_float4(v4.z, v5.z, v6.z, v7.z));
        stcs_f4(o + q + 3l*nq,      make_float4(v0.w, v1.w, v2.w, v3.w));
        stcs_f4(o + q + 3l*nq + 1,  make_float4(v4.w, v5.w, v6.w, v7.w));
    }
    // Tail (n % 8 hits): one thread.
    if (blockIdx.x == 0 && threadIdx.x == 0) {
        for (int i = noct * 8; i < n; i++) {
            float4 v = g_shower[sid[i] + 1];
            out[i]          = v.x;
            out[i + 1ll*n]  = v.y;
            out[i + 2ll*n]  = v.z;
            out[i + 3ll*n]  = v.w;
        }
    }
}

extern "C" void kernel_launch(void* const* d_in, const int* in_sizes, int n_in,
                              void* d_out, int out_size) {
    const int*   pred_sid = (const int*)  d_in[0];
    const float* pcf      = (const float*)d_in[1];
    const float* energy   = (const float*)d_in[2];
    const int*   rid      = (const int*)  d_in[3];
    // d_in[4] = pred_beta (unused)
    const int*   a_tracks = (const int*)  d_in[5];
    const int*   a_hits   = (const int*)  d_in[6];
    float*       out      = (float*)d_out;

    int n_hits    = in_sizes[0];
    int n_showers = in_sizes[5];
    int nseg      = n_showers + 1;
    if (nseg > MAX_SEG) nseg = MAX_SEG;

    static int sm_count = 0;
    if (sm_count == 0) {
        cudaDeviceProp prop;
        cudaGetDeviceProperties(&prop, 0);
        sm_count = prop.multiProcessorCount;
        if (sm_count <= 0) sm_count = 148;
    }

    const int TPB = 256;
    long wave = 8L * sm_count;   // exactly one resident wave @ 8 CTAs/SM

    int ngroups = n_hits / 8;
    long sc_grid = ((long)ngroups + TPB - 1) / TPB;
    if (sc_grid > wave) sc_grid = wave;
    if (sc_grid < 1) sc_grid = 1;
    scatter8_gs_kernel<<<(unsigned)sc_grid, TPB>>>(pred_sid, energy, rid,
                                                   ngroups, n_hits);

    corr_kernel<<<(nseg + TPB - 1) / TPB, TPB>>>(pred_sid, pcf, a_tracks, a_hits,
                                                 n_hits, nseg);

    int noct = n_hits / 8;
    long ga_grid = ((long)noct + TPB - 1) / TPB;
    if (ga_grid > wave) ga_grid = wave;
    if (ga_grid < 1) ga_grid = 1;
    // n divisible by 4 required for the packed float4 stores; guaranteed here
    // (n = 4,000,000) — otherwise the tail loop handles the remainder and the
    // main loop still only touches full octets.
    gather8_gs_kernel<<<(unsigned)ga_grid, TPB>>>(pred_sid, out, noct, n_hits);
}

// round 12
// speedup vs baseline: 1.3066x; 1.3066x over previous
#include <cuda_runtime.h>
#include <cuda_bf16.h>

#define MAX_SEG 16384
#define PAD 32   // one float counter per 128B L2 line

// Padded scatter accumulators: track/hit separated, one counter per 128B
// line. Zero-initialized at module load; corr_kernel self-cleans after
// reading, so every launch starts from a clean state.
__device__ float g_track[MAX_SEG * PAD];
__device__ float g_hit[MAX_SEG * PAD];

// Packed table for the gather phase: ONE 16B read per hit.
//   x = e_track_raw  y = e_track_corr  z = e_hit_raw  w = e_hit_corr
__device__ float4 g_shower[MAX_SEG];

__device__ __forceinline__ void stcs_f4(float4* p, float4 v) {
    asm volatile("st.global.cs.v4.f32 [%0], {%1,%2,%3,%4};"
                 :: "l"(p), "f"(v.x), "f"(v.y), "f"(v.z), "f"(v.w)
                 : "memory");
}
__device__ __forceinline__ int4 ldcs_i4(const int4* p) {
    int4 v;
    asm volatile("ld.global.cs.v4.s32 {%0,%1,%2,%3}, [%4];"
                 : "=r"(v.x), "=r"(v.y), "=r"(v.z), "=r"(v.w) : "l"(p));
    return v;
}
__device__ __forceinline__ float4 ldcs_f4(const float4* p) {
    float4 v;
    asm volatile("ld.global.cs.v4.f32 {%0,%1,%2,%3}, [%4];"
                 : "=f"(v.x), "=f"(v.y), "=f"(v.z), "=f"(v.w) : "l"(p));
    return v;
}

// ---------------------------------------------------------------------------
// Kernel 1: scatter — grid-stride, 8 hits/iter, evict-first streaming loads
// (keep L2 for the hot accumulator lines), then 8 predicated REDs.
// Noise hits (sid == -1) contribute exactly 0 in the reference -> skipped.
// recHitID==1 -> track, ==0 -> hit.
// ---------------------------------------------------------------------------
__global__ void __launch_bounds__(256, 8) scatter8_gs_kernel(
        const int* __restrict__ sid,
        const float* __restrict__ energy,
        const int* __restrict__ rid,
        int ngroups,           // n/8 groups of 8 hits
        int n) {
    int stride = gridDim.x * blockDim.x;
    for (int t = blockIdx.x * blockDim.x + threadIdx.x; t < ngroups;
         t += stride) {
        int4   s0 = ldcs_i4((const int4*)(sid)      + 2*t);
        int4   s1 = ldcs_i4((const int4*)(sid)      + 2*t + 1);
        float4 e0 = ldcs_f4((const float4*)(energy) + 2*t);
        float4 e1 = ldcs_f4((const float4*)(energy) + 2*t + 1);
        int4   r0 = ldcs_i4((const int4*)(rid)      + 2*t);
        int4   r1 = ldcs_i4((const int4*)(rid)      + 2*t + 1);
        int   s[8] = {s0.x, s0.y, s0.z, s0.w, s1.x, s1.y, s1.z, s1.w};
        float e[8] = {e0.x, e0.y, e0.z, e0.w, e1.x, e1.y, e1.z, e1.w};
        int   r[8] = {r0.x, r0.y, r0.z, r0.w, r1.x, r1.y, r1.z, r1.w};
#pragma unroll
        for (int k = 0; k < 8; k++) {
            if (s[k] >= 0) {
                float* p = (r[k] == 1) ? &g_track[(s[k] + 1) * PAD]
                                       : &g_hit[(s[k] + 1) * PAD];
                atomicAdd(p, e[k]);
            }
        }
    }
    // Tail (n % 8 hits): one thread, <= 7 ops.
    if (blockIdx.x == 0 && threadIdx.x == 0) {
        for (int i = ngroups * 8; i < n; i++) {
            int sv = sid[i];
            if (sv >= 0) {
                float* p = (rid[i] == 1) ? &g_track[(sv + 1) * PAD]
                                         : &g_hit[(sv + 1) * PAD];
                atomicAdd(p, energy[i]);
            }
        }
    }
}

// ---------------------------------------------------------------------------
// Kernel 2: per-shower correction + repack into the float4 table + self-clean.
// corr[s] (s>=1) = pcf_ext[alpha_idx[s-1]], pcf_ext[j] = pcf[j] if j < n_hits
// and sid[j] != -1, else 0. corr[0] = 0.
// ---------------------------------------------------------------------------
__global__ void corr_kernel(const int* __restrict__ sid,
                            const float* __restrict__ pcf,
                            const int* __restrict__ a_tracks,
                            const int* __restrict__ a_hits,
                            int n_hits, int nseg) {
    int s = blockIdx.x * blockDim.x + threadIdx.x;
    if (s >= nseg) return;
    float ct = 0.f, ch = 0.f;
    if (s > 0) {
        int jt = a_tracks[s - 1];
        if (jt >= 0 && jt < n_hits && __ldg(sid + jt) != -1) ct = __ldg(pcf + jt);
        int jh = a_hits[s - 1];
        if (jh >= 0 && jh < n_hits && __ldg(sid + jh) != -1) ch = __ldg(pcf + jh);
    }
    float et = g_track[s * PAD];
    float eh = g_hit[s * PAD];
    g_shower[s] = make_float4(et, et * ct, eh, eh * ch);
    g_track[s * PAD] = 0.f;   // clean for the next launch
    g_hit[s * PAD]   = 0.f;
}

// ---------------------------------------------------------------------------
// Kernel 3: gather — grid-stride one wave, 4 hits/iter (EMPIRICAL OPTIMUM —
// 8/iter overflows the per-SM L1tex wavefront queue, replicated twice):
// 1 int4 sid load -> 4 independent random 16B table reads -> 4 coalesced
// float4 STREAMING stores. Output layout (reference tuple order):
//   [0,n) e_track_raw [n,2n) e_track_corr [2n,3n) e_hit_raw [3n,4n) e_hit_corr
// ---------------------------------------------------------------------------
__global__ void __launch_bounds__(256, 8) gather_gs_kernel(
        const int* __restrict__ sid,
        float* __restrict__ out,
        int nquads, int n) {
    int stride = gridDim.x * blockDim.x;
    for (int t = blockIdx.x * blockDim.x + threadIdx.x; t < nquads;
         t += stride) {
        int4 s4 = __ldg((const int4*)(sid) + t);
        float4 v0 = g_shower[s4.x + 1];
        float4 v1 = g_shower[s4.y + 1];
        float4 v2 = g_shower[s4.z + 1];
        float4 v3 = g_shower[s4.w + 1];
        stcs_f4((float4*)(out)          + t, make_float4(v0.x, v1.x, v2.x, v3.x));
        stcs_f4((float4*)(out + n)      + t, make_float4(v0.y, v1.y, v2.y, v3.y));
        stcs_f4((float4*)(out + 2ll*n)  + t, make_float4(v0.z, v1.z, v2.z, v3.z));
        stcs_f4((float4*)(out + 3ll*n)  + t, make_float4(v0.w, v1.w, v2.w, v3.w));
    }
    // Tail (n % 4 hits): one thread.
    if (blockIdx.x == 0 && threadIdx.x == 0) {
        for (int i = nquads * 4; i < n; i++) {
            float4 v = g_shower[sid[i] + 1];
            out[i]          = v.x;
            out[i + 1ll*n]  = v.y;
            out[i + 2ll*n]  = v.z;
            out[i + 3ll*n]  = v.w;
        }
    }
}

extern "C" void kernel_launch(void* const* d_in, const int* in_sizes, int n_in,
                              void* d_out, int out_size) {
    const int*   pred_sid = (const int*)  d_in[0];
    const float* pcf      = (const float*)d_in[1];
    const float* energy   = (const float*)d_in[2];
    const int*   rid      = (const int*)  d_in[3];
    // d_in[4] = pred_beta (unused)
    const int*   a_tracks = (const int*)  d_in[5];
    const int*   a_hits   = (const int*)  d_in[6];
    float*       out      = (float*)d_out;

    int n_hits    = in_sizes[0];
    int n_showers = in_sizes[5];
    int nseg      = n_showers + 1;
    if (nseg > MAX_SEG) nseg = MAX_SEG;

    static int sm_count = 0;
    if (sm_count == 0) {
        cudaDeviceProp prop;
        cudaGetDeviceProperties(&prop, 0);
        sm_count = prop.multiProcessorCount;
        if (sm_count <= 0) sm_count = 148;
    }

    const int TPB = 256;
    long wave = 8L * sm_count;   // exactly one resident wave @ 8 CTAs/SM

    int ngroups = n_hits / 8;
    long sc_grid = ((long)ngroups + TPB - 1) / TPB;
    if (sc_grid > wave) sc_grid = wave;
    if (sc_grid < 1) sc_grid = 1;
    scatter8_gs_kernel<<<(unsigned)sc_grid, TPB>>>(pred_sid, energy, rid,
                                                   ngroups, n_hits);

    corr_kernel<<<(nseg + TPB - 1) / TPB, TPB>>>(pred_sid, pcf, a_tracks, a_hits,
                                                 n_hits, nseg);

    int nquads = n_hits / 4;
    long ga_grid = ((long)nquads + TPB - 1) / TPB;
    if (ga_grid > wave) ga_grid = wave;
    if (ga_grid < 1) ga_grid = 1;
    gather_gs_kernel<<<(unsigned)ga_grid, TPB>>>(pred_sid, out, nquads, n_hits);
}

// round 14
// speedup vs baseline: 1.3279x; 1.0163x over previous
#include <cuda_runtime.h>
#include <cuda_bf16.h>

#define MAX_SEG 16384
#define PAD 32   // one float counter per 128B L2 line

// Padded scatter accumulators: track/hit separated, one counter per 128B
// line. Zero-initialized at module load; corr_kernel self-cleans after
// reading, so every launch starts from a clean state.
__device__ float g_track[MAX_SEG * PAD];
__device__ float g_hit[MAX_SEG * PAD];

// Packed table for the gather phase: ONE 16B read per hit.
//   x = e_track_raw  y = e_track_corr  z = e_hit_raw  w = e_hit_corr
__device__ float4 g_shower[MAX_SEG];

__device__ __forceinline__ void stcs_f4(float4* p, float4 v) {
    asm volatile("st.global.cs.v4.f32 [%0], {%1,%2,%3,%4};"
                 :: "l"(p), "f"(v.x), "f"(v.y), "f"(v.z), "f"(v.w)
                 : "memory");
}
// Evict-last 32B load (8 x b32): keep sid in L2 for the downstream gather.
// ptxas on sm_103 requires .v8.b32 (or .v4.b64) with .L2::evict_last.
__device__ __forceinline__ void ldel_v8(const int* p, int* s) {
    asm volatile(
        "ld.global.L2::evict_last.v8.b32 {%0,%1,%2,%3,%4,%5,%6,%7}, [%8];"
        : "=r"(s[0]), "=r"(s[1]), "=r"(s[2]), "=r"(s[3]),
          "=r"(s[4]), "=r"(s[5]), "=r"(s[6]), "=r"(s[7])
        : "l"(p));
}
// Evict-first: single-use streams.
__device__ __forceinline__ int4 ldcs_i4(const int4* p) {
    int4 v;
    asm volatile("ld.global.cs.v4.s32 {%0,%1,%2,%3}, [%4];"
                 : "=r"(v.x), "=r"(v.y), "=r"(v.z), "=r"(v.w) : "l"(p));
    return v;
}
__device__ __forceinline__ float4 ldcs_f4(const float4* p) {
    float4 v;
    asm volatile("ld.global.cs.v4.f32 {%0,%1,%2,%3}, [%4];"
                 : "=f"(v.x), "=f"(v.y), "=f"(v.z), "=f"(v.w) : "l"(p));
    return v;
}

// ---------------------------------------------------------------------------
// Kernel 1: scatter — grid-stride, 8 hits/iter. sid loaded with one 32B
// evict_last load (reused by gather), energy/rid with evict-first (dead after
// this kernel), then 8 predicated REDs. Noise hits (sid == -1) contribute
// exactly 0 in the reference -> skipped. recHitID==1 -> track, ==0 -> hit.
// ---------------------------------------------------------------------------
__global__ void __launch_bounds__(256, 8) scatter8_gs_kernel(
        const int* __restrict__ sid,
        const float* __restrict__ energy,
        const int* __restrict__ rid,
        int ngroups,           // n/8 groups of 8 hits
        int n) {
    int stride = gridDim.x * blockDim.x;
    for (int t = blockIdx.x * blockDim.x + threadIdx.x; t < ngroups;
         t += stride) {
        int s[8];
        ldel_v8(sid + 8 * t, s);                       // 32B, 32B-aligned
        float4 e0 = ldcs_f4((const float4*)(energy) + 2*t);
        float4 e1 = ldcs_f4((const float4*)(energy) + 2*t + 1);
        int4   r0 = ldcs_i4((const int4*)(rid)      + 2*t);
        int4   r1 = ldcs_i4((const int4*)(rid)      + 2*t + 1);
        float e[8] = {e0.x, e0.y, e0.z, e0.w, e1.x, e1.y, e1.z, e1.w};
        int   r[8] = {r0.x, r0.y, r0.z, r0.w, r1.x, r1.y, r1.z, r1.w};
#pragma unroll
        for (int k = 0; k < 8; k++) {
            if (s[k] >= 0) {
                float* p = (r[k] == 1) ? &g_track[(s[k] + 1) * PAD]
                                       : &g_hit[(s[k] + 1) * PAD];
                atomicAdd(p, e[k]);
            }
        }
    }
    // Tail (n % 8 hits): one thread, <= 7 ops.
    if (blockIdx.x == 0 && threadIdx.x == 0) {
        for (int i = ngroups * 8; i < n; i++) {
            int sv = sid[i];
            if (sv >= 0) {
                float* p = (rid[i] == 1) ? &g_track[(sv + 1) * PAD]
                                         : &g_hit[(sv + 1) * PAD];
                atomicAdd(p, energy[i]);
            }
        }
    }
}

// ---------------------------------------------------------------------------
// Kernel 2: per-shower correction + repack into the float4 table + self-clean.
// corr[s] (s>=1) = pcf_ext[alpha_idx[s-1]], pcf_ext[j] = pcf[j] if j < n_hits
// and sid[j] != -1, else 0. corr[0] = 0.
// ---------------------------------------------------------------------------
__global__ void corr_kernel(const int* __restrict__ sid,
                            const float* __restrict__ pcf,
                            const int* __restrict__ a_tracks,
                            const int* __restrict__ a_hits,
                            int n_hits, int nseg) {
    int s = blockIdx.x * blockDim.x + threadIdx.x;
    if (s >= nseg) return;
    float ct = 0.f, ch = 0.f;
    if (s > 0) {
        int jt = a_tracks[s - 1];
        if (jt >= 0 && jt < n_hits && __ldg(sid + jt) != -1) ct = __ldg(pcf + jt);
        int jh = a_hits[s - 1];
        if (jh >= 0 && jh < n_hits && __ldg(sid + jh) != -1) ch = __ldg(pcf + jh);
    }
    float et = g_track[s * PAD];
    float eh = g_hit[s * PAD];
    g_shower[s] = make_float4(et, et * ct, eh, eh * ch);
    g_track[s * PAD] = 0.f;   // clean for the next launch
    g_hit[s * PAD]   = 0.f;
}

// ---------------------------------------------------------------------------
// Kernel 3: gather — grid-stride one wave, 4 hits/iter (EMPIRICAL OPTIMUM —
// 8/iter overflows the per-SM L1tex wavefront queue, replicated twice):
// 1 int4 sid load (L2-hit thanks to scatter's evict_last) -> 4 independent
// random 16B table reads -> 4 coalesced float4 STREAMING stores.
//   [0,n) e_track_raw [n,2n) e_track_corr [2n,3n) e_hit_raw [3n,4n) e_hit_corr
// ---------------------------------------------------------------------------
__global__ void __launch_bounds__(256, 8) gather_gs_kernel(
        const int* __restrict__ sid,
        float* __restrict__ out,
        int nquads, int n) {
    int stride = gridDim.x * blockDim.x;
    for (int t = blockIdx.x * blockDim.x + threadIdx.x; t < nquads;
         t += stride) {
        int4 s4 = __ldg((const int4*)(sid) + t);
        float4 v0 = g_shower[s4.x + 1];
        float4 v1 = g_shower[s4.y + 1];
        float4 v2 = g_shower[s4.z + 1];
        float4 v3 = g_shower[s4.w + 1];
        stcs_f4((float4*)(out)          + t, make_float4(v0.x, v1.x, v2.x, v3.x));
        stcs_f4((float4*)(out + n)      + t, make_float4(v0.y, v1.y, v2.y, v3.y));
        stcs_f4((float4*)(out + 2ll*n)  + t, make_float4(v0.z, v1.z, v2.z, v3.z));
        stcs_f4((float4*)(out + 3ll*n)  + t, make_float4(v0.w, v1.w, v2.w, v3.w));
    }
    // Tail (n % 4 hits): one thread.
    if (blockIdx.x == 0 && threadIdx.x == 0) {
        for (int i = nquads * 4; i < n; i++) {
            float4 v = g_shower[sid[i] + 1];
            out[i]          = v.x;
            out[i + 1ll*n]  = v.y;
            out[i + 2ll*n]  = v.z;
            out[i + 3ll*n]  = v.w;
        }
    }
}

extern "C" void kernel_launch(void* const* d_in, const int* in_sizes, int n_in,
                              void* d_out, int out_size) {
    const int*   pred_sid = (const int*)  d_in[0];
    const float* pcf      = (const float*)d_in[1];
    const float* energy   = (const float*)d_in[2];
    const int*   rid      = (const int*)  d_in[3];
    // d_in[4] = pred_beta (unused)
    const int*   a_tracks = (const int*)  d_in[5];
    const int*   a_hits   = (const int*)  d_in[6];
    float*       out      = (float*)d_out;

    int n_hits    = in_sizes[0];
    int n_showers = in_sizes[5];
    int nseg      = n_showers + 1;
    if (nseg > MAX_SEG) nseg = MAX_SEG;

    static int sm_count = 0;
    if (sm_count == 0) {
        cudaDeviceProp prop;
        cudaGetDeviceProperties(&prop, 0);
        sm_count = prop.multiProcessorCount;
        if (sm_count <= 0) sm_count = 148;
    }

    const int TPB = 256;
    long wave = 8L * sm_count;   // exactly one resident wave @ 8 CTAs/SM

    int ngroups = n_hits / 8;
    long sc_grid = ((long)ngroups + TPB - 1) / TPB;
    if (sc_grid > wave) sc_grid = wave;
    if (sc_grid < 1) sc_grid = 1;
    scatter8_gs_kernel<<<(unsigned)sc_grid, TPB>>>(pred_sid, energy, rid,
                                                   ngroups, n_hits);

    corr_kernel<<<(nseg + TPB - 1) / TPB, TPB>>>(pred_sid, pcf, a_tracks, a_hits,
                                                 n_hits, nseg);

    int nquads = n_hits / 4;
    long ga_grid = ((long)nquads + TPB - 1) / TPB;
    if (ga_grid > wave) ga_grid = wave;
    if (ga_grid < 1) ga_grid = 1;
    gather_gs_kernel<<<(unsigned)ga_grid, TPB>>>(pred_sid, out, nquads, n_hits);
}